// round 3
// baseline (speedup 1.0000x reference)
#include <cuda_runtime.h>

// ---------------------------------------------------------------------------
// Problem dims
// ---------------------------------------------------------------------------
#define TSTEPS 512
#define NB     64
#define HID    256
#define MROWS  (TSTEPS * NB)      // 32768
#define NCOLS  1024               // 4*HID
#define KDIM   256
#define NCLASS 5

#define GRID_REC 128
#define REC_SMEM ((16384 + 4096) * 4)   // 64KB U slice + 16KB h slice

// ---------------------------------------------------------------------------
// Scratch (static __device__ arrays: allocation-free, allowed)
// ---------------------------------------------------------------------------
__device__ __align__(128) float g_Z [2u * MROWS * NCOLS];   // gate preactivations (reused layer1/layer2)
__device__ __align__(128) float g_H1[2u * MROWS * HID];     // layer-1 hidden outputs
__device__ __align__(128) float g_H2[2u * MROWS * HID];     // layer-2 hidden outputs
__device__ __align__(128) float g_hT[2][2 * 16384];         // double-buffered h, transposed [j][b], per dir
__device__ unsigned g_count = 0;                            // grid barrier
__device__ unsigned g_gen   = 0;
__device__ int      g_tok32 = 1;                            // token dtype flag

// ---------------------------------------------------------------------------
// Helpers
// ---------------------------------------------------------------------------
__device__ __forceinline__ float fsig(float x) {
    x = fminf(fmaxf(x, -30.f), 30.f);
    return __fdividef(1.f, 1.f + __expf(-x));
}
__device__ __forceinline__ float ftanh_(float x) {
    x = fminf(fmaxf(x, -15.f), 15.f);
    float e = __expf(-2.f * x);
    return __fdividef(1.f - e, 1.f + e);
}
__device__ __forceinline__ int load_token(const void* tokens, int is32, int idx) {
    if (is32) return ((const int*)tokens)[idx];
    return (int)((const long long*)tokens)[idx];
}

// ---------------------------------------------------------------------------
// Token dtype probe: int64 little-endian -> all odd int32 words are zero.
// ---------------------------------------------------------------------------
__global__ void tok_probe_kernel(const void* __restrict__ tokens) {
    __shared__ int flag;
    if (threadIdx.x == 0) flag = 0;
    __syncthreads();
    const int* p = (const int*)tokens;
    int local = 0;
    for (int i = 1 + 2 * (int)threadIdx.x; i < MROWS; i += 2 * 256) local |= p[i];
    if (local) atomicOr(&flag, 1);
    __syncthreads();
    if (threadIdx.x == 0) g_tok32 = (flag != 0) ? 1 : 0;
}

// ---------------------------------------------------------------------------
// SGEMM: C[dir] = A @ W[dir] + bias[dir]
//   mode 0: A rows gathered from embedding table via tokens (fw: t=s, bw: t=511-s)
//   mode 1: A = g_H1[dir]   (layer-2 input precompute)
// C = g_Z[dir], shape [MROWS, 1024]. Tiles: 128x128x16, 8x8 per thread.
// ---------------------------------------------------------------------------
__global__ void __launch_bounds__(256) gemm_kernel(
    const float* __restrict__ embed,
    const void*  __restrict__ tokens,
    const float* __restrict__ W_fw,
    const float* __restrict__ W_bw,
    const float* __restrict__ b_fw,
    const float* __restrict__ b_bw,
    int mode)
{
    __shared__ __align__(16) float As[16][132];   // [k][m], padded for bank-free + 16B rows
    __shared__ __align__(16) float Bs[16][128];   // [k][n]
    __shared__ int sTok[128];

    const int tid = threadIdx.x;
    const int dir = blockIdx.z;
    const int m0  = blockIdx.y * 128;
    const int n0  = blockIdx.x * 128;

    const float* Wm   = dir ? W_bw : W_fw;
    const float* bias = dir ? b_bw : b_fw;

    if (mode == 0 && tid < 128) {
        int r = m0 + tid;
        int s = r >> 6, b = r & 63;
        int tt = (dir == 0) ? s : (TSTEPS - 1 - s);
        sTok[tid] = load_token(tokens, g_tok32, b * TSTEPS + tt);
    }
    __syncthreads();

    const int ty = tid >> 4;       // 0..15  (m sub-tile)
    const int tx = tid & 15;       // 0..15  (n sub-tile)

    float acc[8][8];
#pragma unroll
    for (int i = 0; i < 8; i++)
#pragma unroll
        for (int j = 0; j < 8; j++) acc[i][j] = 0.f;

    for (int kt = 0; kt < KDIM; kt += 16) {
        // ---- load A tile (128 rows x 16 k) : 2 float4 per thread ----
#pragma unroll
        for (int i = 0; i < 2; i++) {
            int idx = tid + i * 256;          // 0..511
            int m   = idx >> 2;               // row in tile
            int kq  = idx & 3;                // which float4 along k
            const float* arow;
            if (mode == 0) arow = embed + (size_t)sTok[m] * KDIM;
            else           arow = g_H1 + (size_t)dir * MROWS * HID + (size_t)(m0 + m) * HID;
            float4 v = *(const float4*)(arow + kt + kq * 4);
            As[kq * 4 + 0][m] = v.x;
            As[kq * 4 + 1][m] = v.y;
            As[kq * 4 + 2][m] = v.z;
            As[kq * 4 + 3][m] = v.w;
        }
        // ---- load B tile (16 k x 128 n) : 2 float4 per thread ----
#pragma unroll
        for (int i = 0; i < 2; i++) {
            int idx = tid + i * 256;
            int k   = idx >> 5;               // 0..15
            int nq  = idx & 31;               // 0..31 float4 slots
            *(float4*)&Bs[k][nq * 4] =
                *(const float4*)(Wm + (size_t)(kt + k) * NCOLS + n0 + nq * 4);
        }
        __syncthreads();

#pragma unroll
        for (int kk = 0; kk < 16; kk++) {
            float a[8], bb[8];
            *(float4*)&a[0]  = *(const float4*)&As[kk][ty * 8];
            *(float4*)&a[4]  = *(const float4*)&As[kk][ty * 8 + 4];
            *(float4*)&bb[0] = *(const float4*)&Bs[kk][tx * 8];
            *(float4*)&bb[4] = *(const float4*)&Bs[kk][tx * 8 + 4];
#pragma unroll
            for (int i = 0; i < 8; i++)
#pragma unroll
                for (int j = 0; j < 8; j++)
                    acc[i][j] = fmaf(a[i], bb[j], acc[i][j]);
        }
        __syncthreads();
    }

    // ---- epilogue: += bias, store ----
    float bv[8];
#pragma unroll
    for (int j = 0; j < 8; j++) bv[j] = bias[n0 + tx * 8 + j];

    float* Cd = g_Z + (size_t)dir * MROWS * NCOLS;
#pragma unroll
    for (int i = 0; i < 8; i++) {
        size_t r = (size_t)(m0 + ty * 8 + i);
        float* cp = Cd + r * NCOLS + n0 + tx * 8;
        float4 o0, o1;
        o0.x = acc[i][0] + bv[0]; o0.y = acc[i][1] + bv[1];
        o0.z = acc[i][2] + bv[2]; o0.w = acc[i][3] + bv[3];
        o1.x = acc[i][4] + bv[4]; o1.y = acc[i][5] + bv[5];
        o1.z = acc[i][6] + bv[6]; o1.w = acc[i][7] + bv[7];
        *(float4*)cp       = o0;
        *((float4*)cp + 1) = o1;
    }
}

// ---------------------------------------------------------------------------
// Software grid barrier (all GRID_REC CTAs guaranteed co-resident: 128 <= 148
// SMs, 80KB smem -> 1 CTA/SM). Gen-counter pattern, self-resetting across
// launches; volatile loads bypass L1.
// ---------------------------------------------------------------------------
__device__ __forceinline__ void rec_grid_sync() {
    __threadfence();              // make this thread's h writes visible device-wide
    __syncthreads();
    if (threadIdx.x == 0) {
        volatile unsigned* vgen = &g_gen;
        unsigned cur = *vgen;
        unsigned old = atomicAdd(&g_count, 1);
        if (old == gridDim.x - 1) {
            g_count = 0;
            __threadfence();
            atomicExch((unsigned*)&g_gen, cur + 1);
        } else {
            while (*vgen == cur) { }
        }
    }
    __syncthreads();
    __threadfence();
}

// ---------------------------------------------------------------------------
// Recurrent phase: one launch per layer, both directions concurrently.
// 128 CTAs x 256 thr. CTA = (dir, 16-batch block, 16-hidden block).
// Thread owns one (b, j): c in register for all 512 steps; U slice in SMEM.
// z_t = Z[s] (precomputed x@W+b) + h_{t-1} @ U.
// ---------------------------------------------------------------------------
__global__ void __launch_bounds__(256, 1) rec_kernel(
    const float* __restrict__ U_fw,
    const float* __restrict__ U_bw,
    int layer)
{
    extern __shared__ float smem[];
    float* sU  = smem;            // [k][jl][gate] as float4 per (k,jl): 16384 floats
    float* s_h = smem + 16384;    // [k][bl]: 4096 floats

    const int cid = blockIdx.x;
    const int dir = cid >> 6;
    const int sub = cid & 63;
    const int b0  = (sub >> 4) * 16;
    const int j0  = (sub & 15) * 16;
    const int tid = threadIdx.x;
    const int bl  = tid >> 4;     // 0..15
    const int jl  = tid & 15;     // 0..15
    const int b   = b0 + bl;
    const int j   = j0 + jl;

    const float* U = dir ? U_bw : U_fw;

    // Cache this CTA's U columns (i,f,g,o for j0..j0+15) in SMEM once.
    for (int idx = tid; idx < 16384; idx += 256) {
        int k = idx >> 6, rem = idx & 63;
        int g = rem >> 4, jj = rem & 15;
        sU[(k * 16 + jj) * 4 + g] = U[(size_t)k * NCOLS + g * HID + j0 + jj];
    }
    __syncthreads();

    const float4* U4 = (const float4*)sU;
    const float* Zd  = g_Z + (size_t)dir * MROWS * NCOLS;
    float* Hd        = (layer ? g_H2 : g_H1) + (size_t)dir * MROWS * HID;

    float c = 0.f;
    for (int s = 0; s < TSTEPS; s++) {
        size_t zrow = ((size_t)s * NB + b) * NCOLS;
        float4 acc;
        acc.x = Zd[zrow + 0 * HID + j];
        acc.y = Zd[zrow + 1 * HID + j];
        acc.z = Zd[zrow + 2 * HID + j];
        acc.w = Zd[zrow + 3 * HID + j];

        if (s > 0) {
            // load h_{s-1} slice for our 16 batches (transposed [k][b]); L2-only reads
            const float* src = g_hT[(s - 1) & 1] + dir * 16384;
            for (int idx = tid; idx < 4096; idx += 256) {
                int k = idx >> 4, bb = idx & 15;
                s_h[k * 16 + bb] = __ldcg(&src[k * 64 + b0 + bb]);
            }
            __syncthreads();
#pragma unroll 8
            for (int k = 0; k < HID; k++) {
                float hv = s_h[k * 16 + bl];
                float4 u = U4[k * 16 + jl];
                acc.x = fmaf(u.x, hv, acc.x);
                acc.y = fmaf(u.y, hv, acc.y);
                acc.z = fmaf(u.z, hv, acc.z);
                acc.w = fmaf(u.w, hv, acc.w);
            }
        }

        float ig = fsig(acc.x);
        float fg = fsig(acc.y);
        float gg = ftanh_(acc.z);
        float og = fsig(acc.w);
        c = fg * c + ig * gg;
        float h = og * ftanh_(c);

        g_hT[s & 1][dir * 16384 + j * 64 + b] = h;      // transposed for next step
        Hd[((size_t)s * NB + b) * HID + j] = h;          // sequence output

        if (s < TSTEPS - 1) rec_grid_sync();
    }
}

// ---------------------------------------------------------------------------
// Output head: concat(fw, bw) @ dense_W + b, softmax over 5 classes.
// bw output at position t = bw scan step (T-1-t).
// ---------------------------------------------------------------------------
__global__ void __launch_bounds__(256) dense_kernel(
    const float* __restrict__ Wd,
    const float* __restrict__ bd,
    float* __restrict__ out)
{
    __shared__ float sW[2 * HID * NCLASS];
    __shared__ float sb[NCLASS];
    const int tid = threadIdx.x;
    for (int i = tid; i < 2 * HID * NCLASS; i += 256) sW[i] = Wd[i];
    if (tid < NCLASS) sb[tid] = bd[tid];
    __syncthreads();

    int gid = blockIdx.x * 256 + tid;      // 0..32767 == b*512 + t
    int b = gid >> 9, t = gid & 511;

    const float* hf = g_H2 + ((size_t)t * NB + b) * HID;
    const float* hb = g_H2 + (size_t)MROWS * HID + ((size_t)(TSTEPS - 1 - t) * NB + b) * HID;

    float acc[NCLASS];
#pragma unroll
    for (int cc = 0; cc < NCLASS; cc++) acc[cc] = sb[cc];

    for (int jj = 0; jj < HID; jj++) {
        float v = hf[jj];
#pragma unroll
        for (int cc = 0; cc < NCLASS; cc++)
            acc[cc] = fmaf(v, sW[jj * NCLASS + cc], acc[cc]);
    }
    for (int jj = 0; jj < HID; jj++) {
        float v = hb[jj];
#pragma unroll
        for (int cc = 0; cc < NCLASS; cc++)
            acc[cc] = fmaf(v, sW[(HID + jj) * NCLASS + cc], acc[cc]);
    }

    float m = acc[0];
#pragma unroll
    for (int cc = 1; cc < NCLASS; cc++) m = fmaxf(m, acc[cc]);
    float e[NCLASS], sum = 0.f;
#pragma unroll
    for (int cc = 0; cc < NCLASS; cc++) { e[cc] = __expf(acc[cc] - m); sum += e[cc]; }
    float inv = __fdividef(1.f, sum);
#pragma unroll
    for (int cc = 0; cc < NCLASS; cc++) out[(size_t)gid * NCLASS + cc] = e[cc] * inv;
}

// ---------------------------------------------------------------------------
// Launcher (graph-capturable: kernel launches only, default stream)
// ---------------------------------------------------------------------------
extern "C" void kernel_launch(void* const* d_in, const int* in_sizes, int n_in,
                              void* d_out, int out_size)
{
    const void*  tokens  = d_in[0];
    const float* embed   = (const float*)d_in[1];
    const float* fw_W1   = (const float*)d_in[2];
    const float* fw_U1   = (const float*)d_in[3];
    const float* fw_b1   = (const float*)d_in[4];
    const float* fw_W2   = (const float*)d_in[5];
    const float* fw_U2   = (const float*)d_in[6];
    const float* fw_b2   = (const float*)d_in[7];
    const float* bw_W1   = (const float*)d_in[8];
    const float* bw_U1   = (const float*)d_in[9];
    const float* bw_b1   = (const float*)d_in[10];
    const float* bw_W2   = (const float*)d_in[11];
    const float* bw_U2   = (const float*)d_in[12];
    const float* bw_b2   = (const float*)d_in[13];
    const float* dense_W = (const float*)d_in[14];
    const float* dense_b = (const float*)d_in[15];
    float* out = (float*)d_out;

    cudaFuncSetAttribute(rec_kernel, cudaFuncAttributeMaxDynamicSharedMemorySize, REC_SMEM);

    tok_probe_kernel<<<1, 256>>>(tokens);

    // Z1 = embed(tokens) @ W1 + b1 (both dirs, bw time-reversed)
    gemm_kernel<<<dim3(8, 256, 2), 256>>>(embed, tokens, fw_W1, bw_W1, fw_b1, bw_b1, 0);
    // layer-1 recurrence -> g_H1
    rec_kernel<<<GRID_REC, 256, REC_SMEM>>>(fw_U1, bw_U1, 0);
    // Z2 = H1 @ W2 + b2
    gemm_kernel<<<dim3(8, 256, 2), 256>>>(embed, tokens, fw_W2, bw_W2, fw_b2, bw_b2, 1);
    // layer-2 recurrence -> g_H2
    rec_kernel<<<GRID_REC, 256, REC_SMEM>>>(fw_U2, bw_U2, 1);
    // output head
    dense_kernel<<<MROWS / 256, 256>>>(dense_W, dense_b, out);
}

// round 4
// speedup vs baseline: 1.1433x; 1.1433x over previous
#include <cuda_runtime.h>

// ---------------------------------------------------------------------------
// Problem dims
// ---------------------------------------------------------------------------
#define TSTEPS 512
#define NB     64
#define HID    256
#define MROWS  (TSTEPS * NB)      // 32768
#define NCOLS  1024               // 4*HID
#define KDIM   256
#define NCLASS 5

#define GRID_REC 128
#define SH_STRIDE 260                              // s_h row stride (floats), mult of 4, odd/4 for banks
#define REC_SMEM ((16384 + 16 * SH_STRIDE) * 4)    // 64KB U slice + h slice

// ---------------------------------------------------------------------------
// Scratch (static __device__ arrays: allocation-free, allowed)
// ---------------------------------------------------------------------------
__device__ __align__(128) float g_Z [2u * MROWS * NCOLS];   // gate preactivations
__device__ __align__(128) float g_H1[2u * MROWS * HID];     // layer-1 hidden outputs
__device__ __align__(128) float g_H2[2u * MROWS * HID];     // layer-2 hidden outputs
__device__ __align__(128) float g_hT[2][2 * 16384];         // double-buffered h, [j][b], per dir
__device__ __align__(128) unsigned g_grp[8][32];            // per-group barrier: [g][0]=cnt, [g][1]=gen
__device__ int g_tok32 = 1;                                 // token dtype flag

// ---------------------------------------------------------------------------
// Helpers
// ---------------------------------------------------------------------------
__device__ __forceinline__ float fsig(float x) {
    x = fminf(fmaxf(x, -30.f), 30.f);
    return __fdividef(1.f, 1.f + __expf(-x));
}
__device__ __forceinline__ float ftanh_(float x) {
    x = fminf(fmaxf(x, -15.f), 15.f);
    float e = __expf(-2.f * x);
    return __fdividef(1.f - e, 1.f + e);
}
__device__ __forceinline__ int load_token(const void* tokens, int is32, int idx) {
    if (is32) return ((const int*)tokens)[idx];
    return (int)((const long long*)tokens)[idx];
}

// ---------------------------------------------------------------------------
// Token dtype probe: int64 little-endian -> all odd int32 words are zero.
// ---------------------------------------------------------------------------
__global__ void tok_probe_kernel(const void* __restrict__ tokens) {
    __shared__ int flag;
    if (threadIdx.x == 0) flag = 0;
    __syncthreads();
    const int* p = (const int*)tokens;
    int local = 0;
    for (int i = 1 + 2 * (int)threadIdx.x; i < MROWS; i += 2 * 256) local |= p[i];
    if (local) atomicOr(&flag, 1);
    __syncthreads();
    if (threadIdx.x == 0) g_tok32 = (flag != 0) ? 1 : 0;
}

// ---------------------------------------------------------------------------
// SGEMM: C[dir] = A @ W[dir] + bias[dir]   (unchanged from R2)
// ---------------------------------------------------------------------------
__global__ void __launch_bounds__(256) gemm_kernel(
    const float* __restrict__ embed,
    const void*  __restrict__ tokens,
    const float* __restrict__ W_fw,
    const float* __restrict__ W_bw,
    const float* __restrict__ b_fw,
    const float* __restrict__ b_bw,
    int mode)
{
    __shared__ __align__(16) float As[16][132];
    __shared__ __align__(16) float Bs[16][128];
    __shared__ int sTok[128];

    const int tid = threadIdx.x;
    const int dir = blockIdx.z;
    const int m0  = blockIdx.y * 128;
    const int n0  = blockIdx.x * 128;

    const float* Wm   = dir ? W_bw : W_fw;
    const float* bias = dir ? b_bw : b_fw;

    if (mode == 0 && tid < 128) {
        int r = m0 + tid;
        int s = r >> 6, b = r & 63;
        int tt = (dir == 0) ? s : (TSTEPS - 1 - s);
        sTok[tid] = load_token(tokens, g_tok32, b * TSTEPS + tt);
    }
    __syncthreads();

    const int ty = tid >> 4;
    const int tx = tid & 15;

    float acc[8][8];
#pragma unroll
    for (int i = 0; i < 8; i++)
#pragma unroll
        for (int j = 0; j < 8; j++) acc[i][j] = 0.f;

    for (int kt = 0; kt < KDIM; kt += 16) {
#pragma unroll
        for (int i = 0; i < 2; i++) {
            int idx = tid + i * 256;
            int m   = idx >> 2;
            int kq  = idx & 3;
            const float* arow;
            if (mode == 0) arow = embed + (size_t)sTok[m] * KDIM;
            else           arow = g_H1 + (size_t)dir * MROWS * HID + (size_t)(m0 + m) * HID;
            float4 v = *(const float4*)(arow + kt + kq * 4);
            As[kq * 4 + 0][m] = v.x;
            As[kq * 4 + 1][m] = v.y;
            As[kq * 4 + 2][m] = v.z;
            As[kq * 4 + 3][m] = v.w;
        }
#pragma unroll
        for (int i = 0; i < 2; i++) {
            int idx = tid + i * 256;
            int k   = idx >> 5;
            int nq  = idx & 31;
            *(float4*)&Bs[k][nq * 4] =
                *(const float4*)(Wm + (size_t)(kt + k) * NCOLS + n0 + nq * 4);
        }
        __syncthreads();

#pragma unroll
        for (int kk = 0; kk < 16; kk++) {
            float a[8], bb[8];
            *(float4*)&a[0]  = *(const float4*)&As[kk][ty * 8];
            *(float4*)&a[4]  = *(const float4*)&As[kk][ty * 8 + 4];
            *(float4*)&bb[0] = *(const float4*)&Bs[kk][tx * 8];
            *(float4*)&bb[4] = *(const float4*)&Bs[kk][tx * 8 + 4];
#pragma unroll
            for (int i = 0; i < 8; i++)
#pragma unroll
                for (int j = 0; j < 8; j++)
                    acc[i][j] = fmaf(a[i], bb[j], acc[i][j]);
        }
        __syncthreads();
    }

    float bv[8];
#pragma unroll
    for (int j = 0; j < 8; j++) bv[j] = bias[n0 + tx * 8 + j];

    float* Cd = g_Z + (size_t)dir * MROWS * NCOLS;
#pragma unroll
    for (int i = 0; i < 8; i++) {
        size_t r = (size_t)(m0 + ty * 8 + i);
        float* cp = Cd + r * NCOLS + n0 + tx * 8;
        float4 o0, o1;
        o0.x = acc[i][0] + bv[0]; o0.y = acc[i][1] + bv[1];
        o0.z = acc[i][2] + bv[2]; o0.w = acc[i][3] + bv[3];
        o1.x = acc[i][4] + bv[4]; o1.y = acc[i][5] + bv[5];
        o1.z = acc[i][6] + bv[6]; o1.w = acc[i][7] + bv[7];
        *(float4*)cp       = o0;
        *((float4*)cp + 1) = o1;
    }
}

// ---------------------------------------------------------------------------
// Group-local barrier: 16 CTAs sharing (dir, b-block). 8 independent groups,
// each with its own 128B-padded cnt/gen. Release: fence -> atomicAdd; winner
// resets cnt, fences, flips gen. Acquire: fence after spin.
// ---------------------------------------------------------------------------
__device__ __forceinline__ void group_sync(unsigned* cnt, volatile unsigned* gen) {
    __syncthreads();
    if (threadIdx.x == 0) {
        __threadfence();                       // release my g_hT stores
        unsigned cur = *gen;
        if (atomicAdd(cnt, 1u) == 15u) {
            *cnt = 0;
            __threadfence();
            *gen = cur + 1;
        } else {
            while (*gen == cur) { }
        }
        __threadfence();                       // acquire peers' g_hT stores
    }
    __syncthreads();
}

// ---------------------------------------------------------------------------
// Recurrent phase. 128 CTAs x 256 thr. CTA = (dir, 16-batch blk, 16-hidden blk).
// Thread owns one (b, j): c in register; U slice in SMEM; h slice in SMEM
// transposed [b][k] (stride 260) so hv loads are broadcast LDS.128.
// Z[s+1] prefetched before the barrier; Hd store deferred past arrival.
// ---------------------------------------------------------------------------
__global__ void __launch_bounds__(256, 1) rec_kernel(
    const float* __restrict__ U_fw,
    const float* __restrict__ U_bw,
    int layer)
{
    extern __shared__ float smem[];
    float* sU  = smem;                 // [k][jl] as float4 (4 gates): 16384 floats
    float* s_h = smem + 16384;         // [b_local][k], stride SH_STRIDE

    const int cid = blockIdx.x;
    const int dir = cid >> 6;
    const int sub = cid & 63;
    const int b0  = (sub >> 4) * 16;   // 4 b-blocks
    const int j0  = (sub & 15) * 16;   // 16 j-blocks
    const int tid = threadIdx.x;
    const int bl  = tid >> 4;
    const int jl  = tid & 15;
    const int b   = b0 + bl;
    const int j   = j0 + jl;

    const int grp = dir * 4 + (b0 >> 4);
    unsigned* gcnt = &g_grp[grp][0];
    volatile unsigned* ggen = &g_grp[grp][1];

    const float* U = dir ? U_bw : U_fw;

    // Cache this CTA's U columns (i,f,g,o for j0..j0+15) in SMEM once.
    for (int idx = tid; idx < 16384; idx += 256) {
        int k = idx >> 6, rem = idx & 63;
        int g = rem >> 4, jj = rem & 15;
        sU[(k * 16 + jj) * 4 + g] = U[(size_t)k * NCOLS + g * HID + j0 + jj];
    }
    __syncthreads();

    const float4* U4 = (const float4*)sU;
    const float* Zd  = g_Z + (size_t)dir * MROWS * NCOLS;
    float* Hd        = (layer ? g_H2 : g_H1) + (size_t)dir * MROWS * HID;
    float* hTdir0    = g_hT[0] + dir * 16384;
    float* hTdir1    = g_hT[1] + dir * 16384;

    // first-step Z load
    size_t zrow0 = ((size_t)b) * NCOLS;
    float4 z;
    z.x = Zd[zrow0 + 0 * HID + j];
    z.y = Zd[zrow0 + 1 * HID + j];
    z.z = Zd[zrow0 + 2 * HID + j];
    z.w = Zd[zrow0 + 3 * HID + j];

    float c = 0.f;
    float h_prev_store = 0.f;          // deferred Hd value
    size_t hd_prev_idx = 0;

    for (int s = 0; s < TSTEPS; s++) {
        float4 acc = z;

        if (s > 0) {
            // deferred Hd store from previous step (post-barrier, no fence cost)
            Hd[hd_prev_idx] = h_prev_store;

            // fill s_h[b_local][k] from g_hT[(s-1)&1] (L2-only reads, float4)
            const float* src = ((s - 1) & 1) ? hTdir1 : hTdir0;
            for (int idx = tid; idx < 1024; idx += 256) {
                int k  = idx >> 2;             // 0..255
                int bq = idx & 3;              // 4 batches per float4
                float4 v = __ldcg((const float4*)(src + k * 64 + b0) + bq);
                s_h[(bq * 4 + 0) * SH_STRIDE + k] = v.x;
                s_h[(bq * 4 + 1) * SH_STRIDE + k] = v.y;
                s_h[(bq * 4 + 2) * SH_STRIDE + k] = v.z;
                s_h[(bq * 4 + 3) * SH_STRIDE + k] = v.w;
            }
            __syncthreads();

            const float* hrow = s_h + bl * SH_STRIDE;
#pragma unroll 4
            for (int k = 0; k < HID; k += 8) {
                float4 hA = *(const float4*)(hrow + k);
                float4 hB = *(const float4*)(hrow + k + 4);
                float4 u;
                u = U4[(k + 0) * 16 + jl];
                acc.x = fmaf(u.x, hA.x, acc.x); acc.y = fmaf(u.y, hA.x, acc.y);
                acc.z = fmaf(u.z, hA.x, acc.z); acc.w = fmaf(u.w, hA.x, acc.w);
                u = U4[(k + 1) * 16 + jl];
                acc.x = fmaf(u.x, hA.y, acc.x); acc.y = fmaf(u.y, hA.y, acc.y);
                acc.z = fmaf(u.z, hA.y, acc.z); acc.w = fmaf(u.w, hA.y, acc.w);
                u = U4[(k + 2) * 16 + jl];
                acc.x = fmaf(u.x, hA.z, acc.x); acc.y = fmaf(u.y, hA.z, acc.y);
                acc.z = fmaf(u.z, hA.z, acc.z); acc.w = fmaf(u.w, hA.z, acc.w);
                u = U4[(k + 3) * 16 + jl];
                acc.x = fmaf(u.x, hA.w, acc.x); acc.y = fmaf(u.y, hA.w, acc.y);
                acc.z = fmaf(u.z, hA.w, acc.z); acc.w = fmaf(u.w, hA.w, acc.w);
                u = U4[(k + 4) * 16 + jl];
                acc.x = fmaf(u.x, hB.x, acc.x); acc.y = fmaf(u.y, hB.x, acc.y);
                acc.z = fmaf(u.z, hB.x, acc.z); acc.w = fmaf(u.w, hB.x, acc.w);
                u = U4[(k + 5) * 16 + jl];
                acc.x = fmaf(u.x, hB.y, acc.x); acc.y = fmaf(u.y, hB.y, acc.y);
                acc.z = fmaf(u.z, hB.y, acc.z); acc.w = fmaf(u.w, hB.y, acc.w);
                u = U4[(k + 6) * 16 + jl];
                acc.x = fmaf(u.x, hB.z, acc.x); acc.y = fmaf(u.y, hB.z, acc.y);
                acc.z = fmaf(u.z, hB.z, acc.z); acc.w = fmaf(u.w, hB.z, acc.w);
                u = U4[(k + 7) * 16 + jl];
                acc.x = fmaf(u.x, hB.w, acc.x); acc.y = fmaf(u.y, hB.w, acc.y);
                acc.z = fmaf(u.z, hB.w, acc.z); acc.w = fmaf(u.w, hB.w, acc.w);
            }
        }

        float ig = fsig(acc.x);
        float fg = fsig(acc.y);
        float gg = ftanh_(acc.z);
        float og = fsig(acc.w);
        c = fg * c + ig * gg;
        float h = og * ftanh_(c);

        // h for next step (transposed [j][b]); must be fenced before arrival
        float* hTbuf = (s & 1) ? hTdir1 : hTdir0;
        hTbuf[j * 64 + b] = h;

        // defer the sequence-output store past the barrier
        h_prev_store = h;
        hd_prev_idx  = ((size_t)s * NB + b) * HID + j;

        if (s < TSTEPS - 1) {
            // prefetch Z[s+1] before the barrier (independent of h)
            size_t zrow = ((size_t)(s + 1) * NB + b) * NCOLS;
            z.x = Zd[zrow + 0 * HID + j];
            z.y = Zd[zrow + 1 * HID + j];
            z.z = Zd[zrow + 2 * HID + j];
            z.w = Zd[zrow + 3 * HID + j];
            group_sync(gcnt, (volatile unsigned*)ggen);
        }
    }
    // final Hd store
    Hd[hd_prev_idx] = h_prev_store;
}

// ---------------------------------------------------------------------------
// Output head: concat(fw, bw) @ dense_W + b, softmax over 5 classes.
// ---------------------------------------------------------------------------
__global__ void __launch_bounds__(256) dense_kernel(
    const float* __restrict__ Wd,
    const float* __restrict__ bd,
    float* __restrict__ out)
{
    __shared__ float sW[2 * HID * NCLASS];
    __shared__ float sb[NCLASS];
    const int tid = threadIdx.x;
    for (int i = tid; i < 2 * HID * NCLASS; i += 256) sW[i] = Wd[i];
    if (tid < NCLASS) sb[tid] = bd[tid];
    __syncthreads();

    int gid = blockIdx.x * 256 + tid;      // b*512 + t
    int b = gid >> 9, t = gid & 511;

    const float* hf = g_H2 + ((size_t)t * NB + b) * HID;
    const float* hb = g_H2 + (size_t)MROWS * HID + ((size_t)(TSTEPS - 1 - t) * NB + b) * HID;

    float acc[NCLASS];
#pragma unroll
    for (int cc = 0; cc < NCLASS; cc++) acc[cc] = sb[cc];

    for (int jj = 0; jj < HID; jj++) {
        float v = hf[jj];
#pragma unroll
        for (int cc = 0; cc < NCLASS; cc++)
            acc[cc] = fmaf(v, sW[jj * NCLASS + cc], acc[cc]);
    }
    for (int jj = 0; jj < HID; jj++) {
        float v = hb[jj];
#pragma unroll
        for (int cc = 0; cc < NCLASS; cc++)
            acc[cc] = fmaf(v, sW[(HID + jj) * NCLASS + cc], acc[cc]);
    }

    float m = acc[0];
#pragma unroll
    for (int cc = 1; cc < NCLASS; cc++) m = fmaxf(m, acc[cc]);
    float e[NCLASS], sum = 0.f;
#pragma unroll
    for (int cc = 0; cc < NCLASS; cc++) { e[cc] = __expf(acc[cc] - m); sum += e[cc]; }
    float inv = __fdividef(1.f, sum);
#pragma unroll
    for (int cc = 0; cc < NCLASS; cc++) out[(size_t)gid * NCLASS + cc] = e[cc] * inv;
}

// ---------------------------------------------------------------------------
// Launcher (graph-capturable: kernel launches only, default stream)
// ---------------------------------------------------------------------------
extern "C" void kernel_launch(void* const* d_in, const int* in_sizes, int n_in,
                              void* d_out, int out_size)
{
    const void*  tokens  = d_in[0];
    const float* embed   = (const float*)d_in[1];
    const float* fw_W1   = (const float*)d_in[2];
    const float* fw_U1   = (const float*)d_in[3];
    const float* fw_b1   = (const float*)d_in[4];
    const float* fw_W2   = (const float*)d_in[5];
    const float* fw_U2   = (const float*)d_in[6];
    const float* fw_b2   = (const float*)d_in[7];
    const float* bw_W1   = (const float*)d_in[8];
    const float* bw_U1   = (const float*)d_in[9];
    const float* bw_b1   = (const float*)d_in[10];
    const float* bw_W2   = (const float*)d_in[11];
    const float* bw_U2   = (const float*)d_in[12];
    const float* bw_b2   = (const float*)d_in[13];
    const float* dense_W = (const float*)d_in[14];
    const float* dense_b = (const float*)d_in[15];
    float* out = (float*)d_out;

    cudaFuncSetAttribute(rec_kernel, cudaFuncAttributeMaxDynamicSharedMemorySize, REC_SMEM);

    tok_probe_kernel<<<1, 256>>>(tokens);

    gemm_kernel<<<dim3(8, 256, 2), 256>>>(embed, tokens, fw_W1, bw_W1, fw_b1, bw_b1, 0);
    rec_kernel<<<GRID_REC, 256, REC_SMEM>>>(fw_U1, bw_U1, 0);
    gemm_kernel<<<dim3(8, 256, 2), 256>>>(embed, tokens, fw_W2, bw_W2, fw_b2, bw_b2, 1);
    rec_kernel<<<GRID_REC, 256, REC_SMEM>>>(fw_U2, bw_U2, 1);
    dense_kernel<<<MROWS / 256, 256>>>(dense_W, dense_b, out);
}

// round 5
// speedup vs baseline: 1.1440x; 1.0007x over previous
#include <cuda_runtime.h>

// ---------------------------------------------------------------------------
// Problem dims
// ---------------------------------------------------------------------------
#define TSTEPS 512
#define NB     64
#define HID    256
#define MROWS  (TSTEPS * NB)      // 32768
#define NCOLS  1024               // 4*HID
#define KDIM   256
#define NCLASS 5

#define GRID_REC 128
#define NJ   8                     // j per CTA
#define NBL  32                    // batches per CTA
#define REC_SMEM ((NJ * 4 * KDIM + KDIM * NBL) * 4)   // 32KB U + 32KB h

// ---------------------------------------------------------------------------
// Scratch (static __device__ arrays: allocation-free, allowed)
// ---------------------------------------------------------------------------
__device__ __align__(128) float g_Z [2u * MROWS * NCOLS];   // gate preactivations
__device__ __align__(128) float g_H1[2u * MROWS * HID];     // layer-1 hidden outputs
__device__ __align__(128) float g_H2[2u * MROWS * HID];     // layer-2 hidden outputs
__device__ __align__(128) float g_hT[2][2 * 16384];         // dbl-buffered h, [j][b], per dir
__device__ __align__(128) unsigned g_grp[8][32];            // per-group barrier rows (128B apart)
__device__ int g_tok32 = 1;                                 // token dtype flag

// ---------------------------------------------------------------------------
// Helpers
// ---------------------------------------------------------------------------
__device__ __forceinline__ float fsig(float x) {
    x = fminf(fmaxf(x, -30.f), 30.f);
    return __fdividef(1.f, 1.f + __expf(-x));
}
__device__ __forceinline__ float ftanh_(float x) {
    x = fminf(fmaxf(x, -15.f), 15.f);
    float e = __expf(-2.f * x);
    return __fdividef(1.f - e, 1.f + e);
}
__device__ __forceinline__ int load_token(const void* tokens, int is32, int idx) {
    if (is32) return ((const int*)tokens)[idx];
    return (int)((const long long*)tokens)[idx];
}

// ---------------------------------------------------------------------------
// Token dtype probe: int64 little-endian -> all odd int32 words are zero.
// ---------------------------------------------------------------------------
__global__ void tok_probe_kernel(const void* __restrict__ tokens) {
    __shared__ int flag;
    if (threadIdx.x == 0) flag = 0;
    __syncthreads();
    const int* p = (const int*)tokens;
    int local = 0;
    for (int i = 1 + 2 * (int)threadIdx.x; i < MROWS; i += 2 * 256) local |= p[i];
    if (local) atomicOr(&flag, 1);
    __syncthreads();
    if (threadIdx.x == 0) g_tok32 = (flag != 0) ? 1 : 0;
}

// ---------------------------------------------------------------------------
// SGEMM: C[dir] = A @ W[dir] + bias[dir]   (unchanged)
// ---------------------------------------------------------------------------
__global__ void __launch_bounds__(256) gemm_kernel(
    const float* __restrict__ embed,
    const void*  __restrict__ tokens,
    const float* __restrict__ W_fw,
    const float* __restrict__ W_bw,
    const float* __restrict__ b_fw,
    const float* __restrict__ b_bw,
    int mode)
{
    __shared__ __align__(16) float As[16][132];
    __shared__ __align__(16) float Bs[16][128];
    __shared__ int sTok[128];

    const int tid = threadIdx.x;
    const int dir = blockIdx.z;
    const int m0  = blockIdx.y * 128;
    const int n0  = blockIdx.x * 128;

    const float* Wm   = dir ? W_bw : W_fw;
    const float* bias = dir ? b_bw : b_fw;

    if (mode == 0 && tid < 128) {
        int r = m0 + tid;
        int s = r >> 6, b = r & 63;
        int tt = (dir == 0) ? s : (TSTEPS - 1 - s);
        sTok[tid] = load_token(tokens, g_tok32, b * TSTEPS + tt);
    }
    __syncthreads();

    const int ty = tid >> 4;
    const int tx = tid & 15;

    float acc[8][8];
#pragma unroll
    for (int i = 0; i < 8; i++)
#pragma unroll
        for (int j = 0; j < 8; j++) acc[i][j] = 0.f;

    for (int kt = 0; kt < KDIM; kt += 16) {
#pragma unroll
        for (int i = 0; i < 2; i++) {
            int idx = tid + i * 256;
            int m   = idx >> 2;
            int kq  = idx & 3;
            const float* arow;
            if (mode == 0) arow = embed + (size_t)sTok[m] * KDIM;
            else           arow = g_H1 + (size_t)dir * MROWS * HID + (size_t)(m0 + m) * HID;
            float4 v = *(const float4*)(arow + kt + kq * 4);
            As[kq * 4 + 0][m] = v.x;
            As[kq * 4 + 1][m] = v.y;
            As[kq * 4 + 2][m] = v.z;
            As[kq * 4 + 3][m] = v.w;
        }
#pragma unroll
        for (int i = 0; i < 2; i++) {
            int idx = tid + i * 256;
            int k   = idx >> 5;
            int nq  = idx & 31;
            *(float4*)&Bs[k][nq * 4] =
                *(const float4*)(Wm + (size_t)(kt + k) * NCOLS + n0 + nq * 4);
        }
        __syncthreads();

#pragma unroll
        for (int kk = 0; kk < 16; kk++) {
            float a[8], bb[8];
            *(float4*)&a[0]  = *(const float4*)&As[kk][ty * 8];
            *(float4*)&a[4]  = *(const float4*)&As[kk][ty * 8 + 4];
            *(float4*)&bb[0] = *(const float4*)&Bs[kk][tx * 8];
            *(float4*)&bb[4] = *(const float4*)&Bs[kk][tx * 8 + 4];
#pragma unroll
            for (int i = 0; i < 8; i++)
#pragma unroll
                for (int j = 0; j < 8; j++)
                    acc[i][j] = fmaf(a[i], bb[j], acc[i][j]);
        }
        __syncthreads();
    }

    float bv[8];
#pragma unroll
    for (int j = 0; j < 8; j++) bv[j] = bias[n0 + tx * 8 + j];

    float* Cd = g_Z + (size_t)dir * MROWS * NCOLS;
#pragma unroll
    for (int i = 0; i < 8; i++) {
        size_t r = (size_t)(m0 + ty * 8 + i);
        float* cp = Cd + r * NCOLS + n0 + tx * 8;
        float4 o0, o1;
        o0.x = acc[i][0] + bv[0]; o0.y = acc[i][1] + bv[1];
        o0.z = acc[i][2] + bv[2]; o0.w = acc[i][3] + bv[3];
        o1.x = acc[i][4] + bv[4]; o1.y = acc[i][5] + bv[5];
        o1.z = acc[i][6] + bv[6]; o1.w = acc[i][7] + bv[7];
        *(float4*)cp       = o0;
        *((float4*)cp + 1) = o1;
    }
}

// ---------------------------------------------------------------------------
// Group barrier: 32 CTAs sharing (dir, b-block). 4 independent groups.
// ---------------------------------------------------------------------------
__device__ __forceinline__ void group_sync(unsigned* cnt, volatile unsigned* gen) {
    __syncthreads();
    if (threadIdx.x == 0) {
        __threadfence();                       // release my g_hT stores
        unsigned cur = *gen;
        if (atomicAdd(cnt, 1u) == 31u) {
            *cnt = 0;
            __threadfence();
            *gen = cur + 1;
        } else {
            while (*gen == cur) { }
        }
        __threadfence();                       // acquire peers' g_hT stores
    }
    __syncthreads();
}

// ---------------------------------------------------------------------------
// Recurrent phase. 128 CTAs x 256 thr. CTA = (dir, 8-j block, 32-b block).
// Thread = (b_local, jl): tid = bl*8 + jl. Warp = 4 b x 8 jl, so the U4 load
// is one 128B LDS (4-way broadcast) and h is one broadcast scalar LDS:
// LDS traffic drops ~3.5x vs R3 -> FFMA-bound matvec.
// ---------------------------------------------------------------------------
__global__ void __launch_bounds__(256, 1) rec_kernel(
    const float* __restrict__ U_fw,
    const float* __restrict__ U_bw,
    int layer)
{
    extern __shared__ float smem[];
    float* sU  = smem;                      // [k][jl] float4 of 4 gates: 8192 floats
    float* s_h = smem + NJ * 4 * KDIM;      // [k][bl]: 8192 floats

    const int cid = blockIdx.x;
    const int dir = cid >> 6;
    const int rem = cid & 63;
    const int jb  = rem >> 1;               // 0..31
    const int bb  = rem & 1;                // 0..1
    const int j0  = jb * NJ;
    const int b0  = bb * NBL;
    const int tid = threadIdx.x;
    const int bl  = tid >> 3;               // 0..31
    const int jl  = tid & 7;                // 0..7
    const int b   = b0 + bl;
    const int j   = j0 + jl;

    const int grp = dir * 2 + bb;
    unsigned* gcnt = &g_grp[grp][0];
    volatile unsigned* ggen = (volatile unsigned*)&g_grp[grp][1];

    const float* U = dir ? U_bw : U_fw;

    // Cache U columns: sU[(k*NJ + jl)*4 + g] = U[k][g*HID + j0+jl]
    for (int idx = tid; idx < NJ * 4 * KDIM; idx += 256) {
        int g  = idx & 3;
        int jj = (idx >> 2) & (NJ - 1);
        int k  = idx >> 5;
        sU[idx] = U[(size_t)k * NCOLS + g * HID + j0 + jj];
    }
    __syncthreads();

    const float4* U4 = (const float4*)sU;
    const float* Zd  = g_Z + (size_t)dir * MROWS * NCOLS;
    float* Hd        = (layer ? g_H2 : g_H1) + (size_t)dir * MROWS * HID;
    float* hTdir0    = g_hT[0] + dir * 16384;
    float* hTdir1    = g_hT[1] + dir * 16384;

    // first-step Z load
    size_t zrow0 = ((size_t)b) * NCOLS;
    float4 z;
    z.x = Zd[zrow0 + 0 * HID + j];
    z.y = Zd[zrow0 + 1 * HID + j];
    z.z = Zd[zrow0 + 2 * HID + j];
    z.w = Zd[zrow0 + 3 * HID + j];

    float c = 0.f;
    float h_prev_store = 0.f;
    size_t hd_prev_idx = 0;

    for (int s = 0; s < TSTEPS; s++) {
        float4 acc = z;

        if (s > 0) {
            // deferred Hd store from previous step
            Hd[hd_prev_idx] = h_prev_store;

            // fill s_h[k][bl] from g_hT[(s-1)&1][j][b0..b0+31]  (straight copy)
            const float* src = ((s - 1) & 1) ? hTdir1 : hTdir0;
#pragma unroll
            for (int i = 0; i < 8; i++) {
                int idx = tid + i * 256;            // 0..2047 float4s
                int jr  = idx >> 3;                 // 0..255 (k row)
                int q   = idx & 7;                  // float4 within 32 floats
                float4 v = __ldcg((const float4*)(src + jr * 64 + b0) + q);
                *(float4*)&s_h[jr * NBL + q * 4] = v;
            }
            __syncthreads();

#pragma unroll 16
            for (int k = 0; k < KDIM; k++) {
                float  hv = s_h[k * NBL + bl];
                float4 u  = U4[k * NJ + jl];
                acc.x = fmaf(u.x, hv, acc.x);
                acc.y = fmaf(u.y, hv, acc.y);
                acc.z = fmaf(u.z, hv, acc.z);
                acc.w = fmaf(u.w, hv, acc.w);
            }
        }

        float ig = fsig(acc.x);
        float fg = fsig(acc.y);
        float gg = ftanh_(acc.z);
        float og = fsig(acc.w);
        c = fg * c + ig * gg;
        float h = og * ftanh_(c);

        // h for next step (transposed [j][b]); fenced before barrier arrival
        float* hTbuf = (s & 1) ? hTdir1 : hTdir0;
        hTbuf[j * 64 + b] = h;

        // defer sequence-output store past the barrier
        h_prev_store = h;
        hd_prev_idx  = ((size_t)s * NB + b) * HID + j;

        if (s < TSTEPS - 1) {
            // prefetch Z[s+1] (independent of h) before the barrier
            size_t zrow = ((size_t)(s + 1) * NB + b) * NCOLS;
            z.x = Zd[zrow + 0 * HID + j];
            z.y = Zd[zrow + 1 * HID + j];
            z.z = Zd[zrow + 2 * HID + j];
            z.w = Zd[zrow + 3 * HID + j];
            group_sync(gcnt, ggen);
        }
    }
    Hd[hd_prev_idx] = h_prev_store;
}

// ---------------------------------------------------------------------------
// Output head: concat(fw, bw) @ dense_W + b, softmax over 5 classes.
// ---------------------------------------------------------------------------
__global__ void __launch_bounds__(256) dense_kernel(
    const float* __restrict__ Wd,
    const float* __restrict__ bd,
    float* __restrict__ out)
{
    __shared__ float sW[2 * HID * NCLASS];
    __shared__ float sb[NCLASS];
    const int tid = threadIdx.x;
    for (int i = tid; i < 2 * HID * NCLASS; i += 256) sW[i] = Wd[i];
    if (tid < NCLASS) sb[tid] = bd[tid];
    __syncthreads();

    int gid = blockIdx.x * 256 + tid;      // b*512 + t
    int b = gid >> 9, t = gid & 511;

    const float* hf = g_H2 + ((size_t)t * NB + b) * HID;
    const float* hb = g_H2 + (size_t)MROWS * HID + ((size_t)(TSTEPS - 1 - t) * NB + b) * HID;

    float acc[NCLASS];
#pragma unroll
    for (int cc = 0; cc < NCLASS; cc++) acc[cc] = sb[cc];

    for (int jj = 0; jj < HID; jj++) {
        float v = hf[jj];
#pragma unroll
        for (int cc = 0; cc < NCLASS; cc++)
            acc[cc] = fmaf(v, sW[jj * NCLASS + cc], acc[cc]);
    }
    for (int jj = 0; jj < HID; jj++) {
        float v = hb[jj];
#pragma unroll
        for (int cc = 0; cc < NCLASS; cc++)
            acc[cc] = fmaf(v, sW[(HID + jj) * NCLASS + cc], acc[cc]);
    }

    float m = acc[0];
#pragma unroll
    for (int cc = 1; cc < NCLASS; cc++) m = fmaxf(m, acc[cc]);
    float e[NCLASS], sum = 0.f;
#pragma unroll
    for (int cc = 0; cc < NCLASS; cc++) { e[cc] = __expf(acc[cc] - m); sum += e[cc]; }
    float inv = __fdividef(1.f, sum);
#pragma unroll
    for (int cc = 0; cc < NCLASS; cc++) out[(size_t)gid * NCLASS + cc] = e[cc] * inv;
}

// ---------------------------------------------------------------------------
// Launcher (graph-capturable: kernel launches only, default stream)
// ---------------------------------------------------------------------------
extern "C" void kernel_launch(void* const* d_in, const int* in_sizes, int n_in,
                              void* d_out, int out_size)
{
    const void*  tokens  = d_in[0];
    const float* embed   = (const float*)d_in[1];
    const float* fw_W1   = (const float*)d_in[2];
    const float* fw_U1   = (const float*)d_in[3];
    const float* fw_b1   = (const float*)d_in[4];
    const float* fw_W2   = (const float*)d_in[5];
    const float* fw_U2   = (const float*)d_in[6];
    const float* fw_b2   = (const float*)d_in[7];
    const float* bw_W1   = (const float*)d_in[8];
    const float* bw_U1   = (const float*)d_in[9];
    const float* bw_b1   = (const float*)d_in[10];
    const float* bw_W2   = (const float*)d_in[11];
    const float* bw_U2   = (const float*)d_in[12];
    const float* bw_b2   = (const float*)d_in[13];
    const float* dense_W = (const float*)d_in[14];
    const float* dense_b = (const float*)d_in[15];
    float* out = (float*)d_out;

    cudaFuncSetAttribute(rec_kernel, cudaFuncAttributeMaxDynamicSharedMemorySize, REC_SMEM);

    tok_probe_kernel<<<1, 256>>>(tokens);

    gemm_kernel<<<dim3(8, 256, 2), 256>>>(embed, tokens, fw_W1, bw_W1, fw_b1, bw_b1, 0);
    rec_kernel<<<GRID_REC, 256, REC_SMEM>>>(fw_U1, bw_U1, 0);
    gemm_kernel<<<dim3(8, 256, 2), 256>>>(embed, tokens, fw_W2, bw_W2, fw_b2, bw_b2, 1);
    rec_kernel<<<GRID_REC, 256, REC_SMEM>>>(fw_U2, bw_U2, 1);
    dense_kernel<<<MROWS / 256, 256>>>(dense_W, dense_b, out);
}